// round 1
// baseline (speedup 1.0000x reference)
#include <cuda_runtime.h>

#define BB 16
#define CC_ 128
#define HH 64
#define WW 64
#define SS 16
#define LL (HH*WW)

// Scratch (no allocations allowed)
__device__ float g_xc[BB*LL*CC_];   // conv output (pre-gate), layout [b][l][c]
__device__ float g_dt[BB*LL*CC_];   // dt (sigmoid), layout [b][l][c]
__device__ float g_pooled[BB*CC_];
__device__ float g_gate[BB*CC_];

// ---------------------------------------------------------------------------
__global__ void zero_pooled_kernel() {
    int i = blockIdx.x * blockDim.x + threadIdx.x;
    if (i < BB*CC_) g_pooled[i] = 0.f;
}

// ---------------------------------------------------------------------------
// 3x3 SAME conv, C=128 -> C=128, bias, writes [b][l][co] + pooled partial sums.
// Block: (b, hblock of 8 rows, 16 output channels). 256 threads.
// Thread: 8 cols x 4 consecutive co in registers.
__global__ __launch_bounds__(256) void conv_kernel(
    const float* __restrict__ x,
    const float* __restrict__ cw,
    const float* __restrict__ cbias)
{
    const int b      = blockIdx.z;
    const int h0     = blockIdx.y * 8;
    const int cobase = blockIdx.x * 16;
    const int tid    = threadIdx.x;
    const int cg     = tid & 3;          // co subgroup (4 co each)
    const int sg     = tid >> 2;         // 0..63 spatial group
    const int r      = sg & 7;           // row within hblock (varies within warp)
    const int cb8    = (sg >> 3) << 3;   // col strip base (constant within warp)

    __shared__ float sx[8][10][68];      // [ci][row(-1..8)][col(-1..64)+pad]
    __shared__ float sw[16][73];         // [co][ci*9+tap], pad 73 vs 72
    __shared__ float spool[16];

    float acc[8][4];
#pragma unroll
    for (int p = 0; p < 8; p++)
#pragma unroll
        for (int j = 0; j < 4; j++) acc[p][j] = 0.f;

    for (int cib = 0; cib < CC_; cib += 8) {
        __syncthreads();
        // input patch: 8 ci x 10 rows x 66 cols (zero-padded halo)
        for (int idx = tid; idx < 8*10*66; idx += 256) {
            int ci  = idx / 660;
            int rem = idx - ci*660;
            int rr  = rem / 66;
            int ccx = rem - rr*66;
            int hh  = h0 - 1 + rr;
            int ww  = ccx - 1;
            float v = 0.f;
            if ((unsigned)hh < 64u && (unsigned)ww < 64u)
                v = x[((b*CC_ + cib + ci)*HH + hh)*WW + ww];
            sx[ci][rr][ccx] = v;
        }
        // weights: 16 co x 8 ci x 9 taps
        for (int idx = tid; idx < 16*8*9; idx += 256) {
            int co  = idx / 72;
            int rem = idx - co*72;
            sw[co][rem] = cw[((cobase+co)*CC_ + cib)*9 + rem];
        }
        __syncthreads();

#pragma unroll
        for (int ci = 0; ci < 8; ci++) {
#pragma unroll
            for (int kh = 0; kh < 3; kh++) {
                float xr[10];
#pragma unroll
                for (int t = 0; t < 10; t++) xr[t] = sx[ci][r+kh][cb8 + t];
#pragma unroll
                for (int kw = 0; kw < 3; kw++) {
                    float wv[4];
#pragma unroll
                    for (int j = 0; j < 4; j++)
                        wv[j] = sw[cg*4 + j][ci*9 + kh*3 + kw];
#pragma unroll
                    for (int p = 0; p < 8; p++)
#pragma unroll
                        for (int j = 0; j < 4; j++)
                            acc[p][j] = fmaf(xr[p+kw], wv[j], acc[p][j]);
                }
            }
        }
    }

    if (tid < 16) spool[tid] = 0.f;
    __syncthreads();

    float psum[4] = {0.f, 0.f, 0.f, 0.f};
#pragma unroll
    for (int j = 0; j < 4; j++) {
        float bi = cbias[cobase + cg*4 + j];
#pragma unroll
        for (int p = 0; p < 8; p++) { acc[p][j] += bi; psum[j] += acc[p][j]; }
    }
#pragma unroll
    for (int j = 0; j < 4; j++) atomicAdd(&spool[cg*4 + j], psum[j]);

#pragma unroll
    for (int p = 0; p < 8; p++) {
        int l = (h0 + r)*WW + cb8 + p;
        float4 v = make_float4(acc[p][0], acc[p][1], acc[p][2], acc[p][3]);
        *reinterpret_cast<float4*>(&g_xc[(b*LL + l)*CC_ + cobase + cg*4]) = v;
    }
    __syncthreads();
    if (tid < 16) atomicAdd(&g_pooled[b*CC_ + cobase + tid], spool[tid]);
}

// ---------------------------------------------------------------------------
// Spectral gate: pooled mean -> fc(relu) -> fc(sigmoid). One block per batch.
__global__ __launch_bounds__(128) void gate_kernel(
    const float* __restrict__ g1w, const float* __restrict__ g1b,
    const float* __restrict__ g2w, const float* __restrict__ g2b)
{
    const int b = blockIdx.x;
    const int o = threadIdx.x;
    __shared__ float sp[CC_], st[CC_];
    sp[o] = g_pooled[b*CC_ + o] * (1.f/(float)LL);
    __syncthreads();
    float a1 = g1b[o];
    for (int c = 0; c < CC_; c++) a1 = fmaf(sp[c], g1w[o*CC_ + c], a1);
    st[o] = fmaxf(a1, 0.f);
    __syncthreads();
    float a2 = g2b[o];
    for (int c = 0; c < CC_; c++) a2 = fmaf(st[c], g2w[o*CC_ + c], a2);
    g_gate[b*CC_ + o] = 1.f / (1.f + __expf(-a2));
}

// ---------------------------------------------------------------------------
// dt = sigmoid( (xc * g) @ dt_w^T + dt_b ).  M=65536, N=128, K=128.
// Block: 64 rows x 128 cols, 256 threads, thread = 8 rows x 4 cols.
__global__ __launch_bounds__(256) void dt_kernel(
    const float* __restrict__ dtw, const float* __restrict__ dtb)
{
    const int m0   = blockIdx.x * 64;
    const int b    = m0 >> 12;            // 4096 tokens per batch
    const int tid  = threadIdx.x;
    const int colg = tid & 31;
    const int rowg = tid >> 5;

    __shared__ float xs[64*33];
    __shared__ float ws[128*33];

    float acc[8][4];
#pragma unroll
    for (int p = 0; p < 8; p++)
#pragma unroll
        for (int j = 0; j < 4; j++) acc[p][j] = 0.f;

    for (int kb = 0; kb < CC_; kb += 32) {
        __syncthreads();
        for (int idx = tid; idx < 64*32; idx += 256) {
            int rr = idx >> 5, k = idx & 31;
            xs[rr*33 + k] = g_xc[(m0+rr)*CC_ + kb + k] * g_gate[b*CC_ + kb + k];
        }
        for (int idx = tid; idx < 128*32; idx += 256) {
            int co = idx >> 5, k = idx & 31;
            ws[co*33 + k] = dtw[co*CC_ + kb + k];
        }
        __syncthreads();
#pragma unroll
        for (int k = 0; k < 32; k++) {
            float xv[8], wv[4];
#pragma unroll
            for (int p = 0; p < 8; p++) xv[p] = xs[(rowg*8+p)*33 + k];
#pragma unroll
            for (int j = 0; j < 4; j++) wv[j] = ws[(colg*4+j)*33 + k];
#pragma unroll
            for (int p = 0; p < 8; p++)
#pragma unroll
                for (int j = 0; j < 4; j++)
                    acc[p][j] = fmaf(xv[p], wv[j], acc[p][j]);
        }
    }
#pragma unroll
    for (int p = 0; p < 8; p++) {
        float4 v;
        float* vv = reinterpret_cast<float*>(&v);
#pragma unroll
        for (int j = 0; j < 4; j++) {
            float z = acc[p][j] + dtb[colg*4 + j];
            vv[j] = 1.f / (1.f + __expf(-z));
        }
        *reinterpret_cast<float4*>(&g_dt[(m0 + rowg*8 + p)*CC_ + colg*4]) = v;
    }
}

// ---------------------------------------------------------------------------
// SSM scan over L=4096 tokens. Block: (b, 16 channels). Lane = state s (16 per
// channel, 2 channels per warp). y reduced via shfl butterfly. Chunks of 64
// tokens staged in smem for coalesced global traffic. Adds identity, writes NCHW.
__global__ __launch_bounds__(256) void scan_kernel(
    const float* __restrict__ x0,
    const float* __restrict__ Araw,
    const float* __restrict__ Draw,
    float* __restrict__ out)
{
    const int b     = blockIdx.x >> 3;
    const int cbase = (blockIdx.x & 7) << 4;
    const int tid   = threadIdx.x;
    const int lane  = tid & 31;
    const int wid   = tid >> 5;
    const int cl    = wid*2 + (lane >> 4);   // 0..15 local channel
    const int c     = cbase + cl;
    const int s     = lane & 15;

    __shared__ float sxs[64*17], sdt[64*17], syv[64*17];

    const float Anr = -__expf(Araw[c*SS + s]);
    const float Dpc = __expf(Draw[c]);
    const float gc  = g_gate[b*CC_ + c];
    float h = 0.f;

    const int basex = b*LL*CC_ + cbase;
    for (int ch = 0; ch < LL/64; ch++) {
        const int l0 = ch*64;
#pragma unroll
        for (int i = 0; i < 4; i++) {
            int idx = tid + i*256;
            int ll = idx >> 4, ccx = idx & 15;
            int ga = basex + (l0 + ll)*CC_ + ccx;
            sxs[ll*17 + ccx] = g_xc[ga];
            sdt[ll*17 + ccx] = g_dt[ga];
        }
        __syncthreads();
#pragma unroll 4
        for (int l = 0; l < 64; l++) {
            float xv  = sxs[l*17 + cl] * gc;
            float dtv = sdt[l*17 + cl];
            float a   = __expf(Anr * dtv);
            h = fmaf(h, a, xv);
            float part = h * Anr;
            part += __shfl_xor_sync(0xffffffffu, part, 8);
            part += __shfl_xor_sync(0xffffffffu, part, 4);
            part += __shfl_xor_sync(0xffffffffu, part, 2);
            part += __shfl_xor_sync(0xffffffffu, part, 1);
            if (s == 0) syv[l*17 + cl] = part + Dpc * xv;
        }
        __syncthreads();
#pragma unroll
        for (int i = 0; i < 4; i++) {
            int idx = tid + i*256;
            int ccx = idx >> 6, ll = idx & 63;
            int ga = ((b*CC_ + cbase + ccx) << 12) + l0 + ll;
            out[ga] = syv[ll*17 + ccx] + x0[ga];
        }
        __syncthreads();
    }
}

// ---------------------------------------------------------------------------
extern "C" void kernel_launch(void* const* d_in, const int* in_sizes, int n_in,
                              void* d_out, int out_size)
{
    const float* x      = (const float*)d_in[0];
    const float* conv_w = (const float*)d_in[1];
    const float* conv_b = (const float*)d_in[2];
    const float* dt_w   = (const float*)d_in[3];
    const float* dt_b   = (const float*)d_in[4];
    const float* A      = (const float*)d_in[5];
    const float* D      = (const float*)d_in[6];
    const float* g1_w   = (const float*)d_in[7];
    const float* g1_b   = (const float*)d_in[8];
    const float* g2_w   = (const float*)d_in[9];
    const float* g2_b   = (const float*)d_in[10];
    float* out = (float*)d_out;

    zero_pooled_kernel<<<8, 256>>>();
    conv_kernel<<<dim3(8, 8, BB), 256>>>(x, conv_w, conv_b);
    gate_kernel<<<BB, 128>>>(g1_w, g1_b, g2_w, g2_b);
    dt_kernel<<<(BB*LL)/64, 256>>>(dt_w, dt_b);
    scan_kernel<<<BB*8, 256>>>(x, A, D, out);
}

// round 3
// speedup vs baseline: 1.2290x; 1.2290x over previous
#include <cuda_runtime.h>
#include <cuda_bf16.h>
#include <cstdint>

#define BB 16
#define CC_ 128
#define HH 64
#define WW 64
#define SS 16
#define LL (HH*WW)

// ---------------------------------------------------------------------------
// Scratch (no allocations allowed)
__device__ float g_xc[BB*LL*CC_];                         // conv output [b][l][c]
__device__ float g_dt[BB*LL*CC_];                         // dt sigmoid [b][l][c]
__device__ float g_pooled[BB*CC_];
__device__ float g_gate[BB*CC_];
__device__ __align__(16) __nv_bfloat16 g_xpad[BB*66*66*256];   // [b][r][c][hi128|lo128]
__device__ __align__(16) __nv_bfloat16 g_wp[9*2*128*128];      // [tap][var][co][ci]

// ---------------------------------------------------------------------------
__device__ __forceinline__ uint32_t smem_u32(const void* p) {
    uint32_t a;
    asm("{ .reg .u64 t; cvta.to.shared.u64 t, %1; cvt.u32.u64 %0, t; }" : "=r"(a) : "l"(p));
    return a;
}
__device__ __forceinline__ void cp16(uint32_t dst, const void* src) {
    asm volatile("cp.async.cg.shared.global [%0], [%1], 16;" :: "r"(dst), "l"(src));
}
__device__ __forceinline__ void cp_commit() { asm volatile("cp.async.commit_group;" ::: "memory"); }
template<int N> __device__ __forceinline__ void cp_wait() {
    asm volatile("cp.async.wait_group %0;" :: "n"(N) : "memory");
}
__device__ __forceinline__ void ldsm_x4(uint32_t& r0, uint32_t& r1, uint32_t& r2, uint32_t& r3, uint32_t addr) {
    asm volatile("ldmatrix.sync.aligned.m8n8.x4.shared.b16 {%0,%1,%2,%3}, [%4];"
        : "=r"(r0), "=r"(r1), "=r"(r2), "=r"(r3) : "r"(addr));
}
__device__ __forceinline__ void mma16816(float* c, uint32_t a0, uint32_t a1, uint32_t a2, uint32_t a3,
                                         uint32_t b0, uint32_t b1) {
    asm volatile("mma.sync.aligned.m16n8k16.row.col.f32.bf16.bf16.f32 "
        "{%0,%1,%2,%3}, {%4,%5,%6,%7}, {%8,%9}, {%0,%1,%2,%3};"
        : "+f"(c[0]), "+f"(c[1]), "+f"(c[2]), "+f"(c[3])
        : "r"(a0), "r"(a1), "r"(a2), "r"(a3), "r"(b0), "r"(b1));
}

// ---------------------------------------------------------------------------
__global__ void zero_pooled_kernel() {
    int i = blockIdx.x * blockDim.x + threadIdx.x;
    if (i < BB*CC_) g_pooled[i] = 0.f;
}

// ---------------------------------------------------------------------------
// prep_x: x (fp32 NCHW) -> padded channels-last bf16 hi/lo [b][66][66][256]
// element e<128: hi of channel e; e>=128: lo residual of channel e-128.
__global__ __launch_bounds__(256) void prep_x_kernel(const float* __restrict__ x)
{
    const int pr = blockIdx.x;   // padded row 0..65
    const int b  = blockIdx.y;
    const int tid = threadIdx.x;
    uint32_t* outw = reinterpret_cast<uint32_t*>(g_xpad) + ((b*66 + pr)*66) * 128;

    if (pr == 0 || pr == 65) {
        for (int i = tid; i < 66*128; i += 256) outw[i] = 0u;
        return;
    }
    const int hr = pr - 1;
    __shared__ float tile[128*64];
    for (int i = tid; i < 128*64; i += 256) {
        int c = i >> 6, w = i & 63;
        tile[i] = x[((b*CC_ + c)*HH + hr)*WW + w];
    }
    __syncthreads();
    for (int i = tid; i < 66*128; i += 256) {
        int pc = i >> 7, j = i & 127;
        uint32_t v = 0u;
        if (pc >= 1 && pc <= 64) {
            int w = pc - 1;
            int c0 = (j < 64) ? (j*2) : ((j-64)*2);
            float v0 = tile[c0*64 + w], v1 = tile[(c0+1)*64 + w];
            __nv_bfloat16 h0 = __float2bfloat16(v0), h1 = __float2bfloat16(v1);
            __nv_bfloat16 o0, o1;
            if (j < 64) { o0 = h0; o1 = h1; }
            else {
                o0 = __float2bfloat16(v0 - __bfloat162float(h0));
                o1 = __float2bfloat16(v1 - __bfloat162float(h1));
            }
            v = (uint32_t)*reinterpret_cast<uint16_t*>(&o0) |
                ((uint32_t)*reinterpret_cast<uint16_t*>(&o1) << 16);
        }
        outw[i] = v;
    }
}

// prep_w: conv_w [co][ci][3][3] fp32 -> g_wp[tap][var][co][ci] bf16 (var0=hi, var1=lo)
__global__ __launch_bounds__(256) void prep_w_kernel(const float* __restrict__ cw)
{
    int idx = blockIdx.x * 256 + threadIdx.x;
    if (idx >= 9*2*128*128) return;
    int t   = idx >> 15;
    int var = (idx >> 14) & 1;
    int co  = (idx >> 7) & 127;
    int ci  = idx & 127;
    float w = cw[(co*CC_ + ci)*9 + t];
    __nv_bfloat16 hi = __float2bfloat16(w);
    g_wp[idx] = (var == 0) ? hi : __float2bfloat16(w - __bfloat162float(hi));
}

// ---------------------------------------------------------------------------
// Implicit-GEMM conv via warp-level HMMA (mma.sync m16n8k16 bf16).
// CTA: M=128 tokens (2 output rows) x N=128 co. 8 warps: 4m x 2n, warp 32x64.
// 54 stages of K=64: 9 taps x {xh.wh(lo/hi ci), xl.wh(lo/hi), xh.wl(lo/hi)}.
// SMEM per stage: A[128][64] and B[128][64] bf16, row stride 72 elems (144 B).
#define ROWSTRIDE 144

__global__ __launch_bounds__(256, 2) void conv_mma_kernel(const float* __restrict__ cbias)
{
    extern __shared__ char dyn[];
    const uint32_t sbase = smem_u32(dyn);
    const uint32_t abuf[2] = { sbase,           sbase + 36864 };
    const uint32_t bbuf[2] = { sbase + 18432,   sbase + 36864 + 18432 };

    const int tid  = threadIdx.x;
    const int wid  = tid >> 5;
    const int lane = tid & 31;
    const int mw   = wid & 3;          // 4 m-warps
    const int nw   = wid >> 2;         // 2 n-warps
    const int b    = blockIdx.x >> 5;
    const int tile = blockIdx.x & 31;  // 2 output rows per tile
    const int R    = tile * 2;

    float acc[2][8][4];
#pragma unroll
    for (int m = 0; m < 2; m++)
#pragma unroll
        for (int n = 0; n < 8; n++)
#pragma unroll
            for (int j = 0; j < 4; j++) acc[m][n][j] = 0.f;

    const __nv_bfloat16* xp = g_xpad;
    const __nv_bfloat16* wp = g_wp;

    auto issue_loads = [&](int s, uint32_t ab, uint32_t bb) {
        const int t_  = s / 6;
        const int sub = s - t_*6;
        const int kh  = t_ / 3, kw = t_ - kh*3;
        const int choff = ((sub >= 2 && sub < 4) ? 128 : 0) + ((sub & 1) << 6);
        const int cioff = (sub & 1) << 6;
        const int var   = (sub >= 4) ? 1 : 0;
        const __nv_bfloat16* wrow = wp + (long)((t_*2 + var)*128) * 128 + cioff;
#pragma unroll
        for (int i = 0; i < 4; i++) {
            int idx = tid + i*256;
            int tk  = idx >> 3;       // token (A) / co (B)
            int k8  = idx & 7;        // 16B chunk within 64-k row
            // A
            {
                int prow = R + kh + (tk >> 6);
                int pcol = kw + (tk & 63);
                long gi = ((long)((b*66 + prow)*66 + pcol) << 8) + choff + (k8 << 3);
                cp16(ab + tk*ROWSTRIDE + k8*16, xp + gi);
            }
            // B
            cp16(bb + tk*ROWSTRIDE + k8*16, wrow + (long)tk*128 + (k8 << 3));
        }
    };

    issue_loads(0, abuf[0], bbuf[0]);
    cp_commit();

    // ldmatrix lane addressing offsets (row within 16-row tile, +16B for hi half)
    const uint32_t lrow = (lane & 15);
    const uint32_t lhalf = (lane >> 4) * 16;

    for (int s = 0; s < 54; s++) {
        if (s + 1 < 54) {
            int bn = (s + 1) & 1;
            issue_loads(s + 1, abuf[bn], bbuf[bn]);
            cp_commit();
            cp_wait<1>();
        } else {
            cp_wait<0>();
        }
        __syncthreads();

        const uint32_t ab = abuf[s & 1], bb = bbuf[s & 1];
        const uint32_t a0 = ab + (mw*32 + lrow)*ROWSTRIDE + lhalf;       // m-tile 0
        const uint32_t a1 = ab + (mw*32 + 16 + lrow)*ROWSTRIDE + lhalf;  // m-tile 1
        const uint32_t bbase = bb + (nw*64 + lrow)*ROWSTRIDE + lhalf;

#pragma unroll
        for (int ks = 0; ks < 4; ks++) {
            uint32_t af[2][4];
            ldsm_x4(af[0][0], af[0][1], af[0][2], af[0][3], a0 + ks*32);
            ldsm_x4(af[1][0], af[1][1], af[1][2], af[1][3], a1 + ks*32);
            uint32_t bf[8][2];
#pragma unroll
            for (int q = 0; q < 4; q++) {
                uint32_t r0, r1, r2, r3;
                ldsm_x4(r0, r1, r2, r3, bbase + q*16*ROWSTRIDE + ks*32);
                bf[q*2][0] = r0;   bf[q*2][1] = r2;
                bf[q*2+1][0] = r1; bf[q*2+1][1] = r3;
            }
#pragma unroll
            for (int m = 0; m < 2; m++)
#pragma unroll
                for (int n = 0; n < 8; n++)
                    mma16816(acc[m][n], af[m][0], af[m][1], af[m][2], af[m][3],
                             bf[n][0], bf[n][1]);
        }
        __syncthreads();
    }

    // Epilogue: add bias, store fp32 to g_xc [token][co]
    const int qrow = lane >> 2;              // 0..7
    const int qcol = (lane & 3) * 2;         // 0,2,4,6
    const long tokbase = (long)(b << 12) + tile*128 + mw*32;
#pragma unroll
    for (int n = 0; n < 8; n++) {
        const int co = nw*64 + n*8 + qcol;
        const float b0 = cbias[co], b1 = cbias[co + 1];
#pragma unroll
        for (int m = 0; m < 2; m++) {
            long t0 = tokbase + m*16 + qrow;
            float2 v0 = make_float2(acc[m][n][0] + b0, acc[m][n][1] + b1);
            float2 v1 = make_float2(acc[m][n][2] + b0, acc[m][n][3] + b1);
            *reinterpret_cast<float2*>(g_xc + t0*CC_ + co) = v0;
            *reinterpret_cast<float2*>(g_xc + (t0 + 8)*CC_ + co) = v1;
        }
    }
}

// ---------------------------------------------------------------------------
// pooled sums (post-conv): g_pooled[b][c] = sum_l g_xc[b][l][c]
__global__ __launch_bounds__(256) void pool_kernel()
{
    const int b  = blockIdx.x;
    const int lc = blockIdx.y;
    const int tid = threadIdx.x;
    const int c = tid & 127, half = tid >> 7;
    float s = 0.f;
    for (int l = lc*256 + half; l < lc*256 + 256; l += 2)
        s += g_xc[((long)(b << 12) + l)*CC_ + c];
    __shared__ float sp[256];
    sp[tid] = s;
    __syncthreads();
    if (tid < 128) atomicAdd(&g_pooled[b*CC_ + tid], sp[tid] + sp[tid + 128]);
}

// ---------------------------------------------------------------------------
__global__ __launch_bounds__(128) void gate_kernel(
    const float* __restrict__ g1w, const float* __restrict__ g1b,
    const float* __restrict__ g2w, const float* __restrict__ g2b)
{
    const int b = blockIdx.x;
    const int o = threadIdx.x;
    __shared__ float sp[CC_], st[CC_];
    sp[o] = g_pooled[b*CC_ + o] * (1.f/(float)LL);
    __syncthreads();
    float a1 = g1b[o];
    for (int c = 0; c < CC_; c++) a1 = fmaf(sp[c], g1w[o*CC_ + c], a1);
    st[o] = fmaxf(a1, 0.f);
    __syncthreads();
    float a2 = g2b[o];
    for (int c = 0; c < CC_; c++) a2 = fmaf(st[c], g2w[o*CC_ + c], a2);
    g_gate[b*CC_ + o] = 1.f / (1.f + __expf(-a2));
}

// ---------------------------------------------------------------------------
__global__ __launch_bounds__(256) void dt_kernel(
    const float* __restrict__ dtw, const float* __restrict__ dtb)
{
    const int m0   = blockIdx.x * 64;
    const int b    = m0 >> 12;
    const int tid  = threadIdx.x;
    const int colg = tid & 31;
    const int rowg = tid >> 5;

    __shared__ float xs[64*33];
    __shared__ float ws[128*33];

    float acc[8][4];
#pragma unroll
    for (int p = 0; p < 8; p++)
#pragma unroll
        for (int j = 0; j < 4; j++) acc[p][j] = 0.f;

    for (int kb = 0; kb < CC_; kb += 32) {
        __syncthreads();
        for (int idx = tid; idx < 64*32; idx += 256) {
            int rr = idx >> 5, k = idx & 31;
            xs[rr*33 + k] = g_xc[(m0+rr)*CC_ + kb + k] * g_gate[b*CC_ + kb + k];
        }
        for (int idx = tid; idx < 128*32; idx += 256) {
            int co = idx >> 5, k = idx & 31;
            ws[co*33 + k] = dtw[co*CC_ + kb + k];
        }
        __syncthreads();
#pragma unroll
        for (int k = 0; k < 32; k++) {
            float xv[8], wv[4];
#pragma unroll
            for (int p = 0; p < 8; p++) xv[p] = xs[(rowg*8+p)*33 + k];
#pragma unroll
            for (int j = 0; j < 4; j++) wv[j] = ws[(colg*4+j)*33 + k];
#pragma unroll
            for (int p = 0; p < 8; p++)
#pragma unroll
                for (int j = 0; j < 4; j++)
                    acc[p][j] = fmaf(xv[p], wv[j], acc[p][j]);
        }
    }
#pragma unroll
    for (int p = 0; p < 8; p++) {
        float4 v;
        float* vv = reinterpret_cast<float*>(&v);
#pragma unroll
        for (int j = 0; j < 4; j++) {
            float z = acc[p][j] + dtb[colg*4 + j];
            vv[j] = 1.f / (1.f + __expf(-z));
        }
        *reinterpret_cast<float4*>(&g_dt[(m0 + rowg*8 + p)*CC_ + colg*4]) = v;
    }
}

// ---------------------------------------------------------------------------
__global__ __launch_bounds__(256) void scan_kernel(
    const float* __restrict__ x0,
    const float* __restrict__ Araw,
    const float* __restrict__ Draw,
    float* __restrict__ out)
{
    const int b     = blockIdx.x >> 3;
    const int cbase = (blockIdx.x & 7) << 4;
    const int tid   = threadIdx.x;
    const int lane  = tid & 31;
    const int wid   = tid >> 5;
    const int cl    = wid*2 + (lane >> 4);
    const int c     = cbase + cl;
    const int s     = lane & 15;

    __shared__ float sxs[64*17], sdt[64*17], syv[64*17];

    const float Anr = -__expf(Araw[c*SS + s]);
    const float Dpc = __expf(Draw[c]);
    const float gc  = g_gate[b*CC_ + c];
    float h = 0.f;

    const int basex = b*LL*CC_ + cbase;
    for (int ch = 0; ch < LL/64; ch++) {
        const int l0 = ch*64;
#pragma unroll
        for (int i = 0; i < 4; i++) {
            int idx = tid + i*256;
            int ll = idx >> 4, ccx = idx & 15;
            int ga = basex + (l0 + ll)*CC_ + ccx;
            sxs[ll*17 + ccx] = g_xc[ga];
            sdt[ll*17 + ccx] = g_dt[ga];
        }
        __syncthreads();
#pragma unroll 4
        for (int l = 0; l < 64; l++) {
            float xv  = sxs[l*17 + cl] * gc;
            float dtv = sdt[l*17 + cl];
            float a   = __expf(Anr * dtv);
            h = fmaf(h, a, xv);
            float part = h * Anr;
            part += __shfl_xor_sync(0xffffffffu, part, 8);
            part += __shfl_xor_sync(0xffffffffu, part, 4);
            part += __shfl_xor_sync(0xffffffffu, part, 2);
            part += __shfl_xor_sync(0xffffffffu, part, 1);
            if (s == 0) syv[l*17 + cl] = part + Dpc * xv;
        }
        __syncthreads();
#pragma unroll
        for (int i = 0; i < 4; i++) {
            int idx = tid + i*256;
            int ccx = idx >> 6, ll = idx & 63;
            int ga = ((b*CC_ + cbase + ccx) << 12) + l0 + ll;
            out[ga] = syv[ll*17 + ccx] + x0[ga];
        }
        __syncthreads();
    }
}

// ---------------------------------------------------------------------------
extern "C" void kernel_launch(void* const* d_in, const int* in_sizes, int n_in,
                              void* d_out, int out_size)
{
    const float* x      = (const float*)d_in[0];
    const float* conv_w = (const float*)d_in[1];
    const float* conv_b = (const float*)d_in[2];
    const float* dt_w   = (const float*)d_in[3];
    const float* dt_b   = (const float*)d_in[4];
    const float* A      = (const float*)d_in[5];
    const float* D      = (const float*)d_in[6];
    const float* g1_w   = (const float*)d_in[7];
    const float* g1_b   = (const float*)d_in[8];
    const float* g2_w   = (const float*)d_in[9];
    const float* g2_b   = (const float*)d_in[10];
    float* out = (float*)d_out;

    const int conv_smem = 2 * (18432 + 18432);   // 73728 B
    cudaFuncSetAttribute(conv_mma_kernel, cudaFuncAttributeMaxDynamicSharedMemorySize, conv_smem);

    zero_pooled_kernel<<<8, 256>>>();
    prep_x_kernel<<<dim3(66, BB), 256>>>(x);
    prep_w_kernel<<<(9*2*128*128 + 255)/256, 256>>>(conv_w);
    conv_mma_kernel<<<BB*32, 256, conv_smem>>>(conv_b);
    pool_kernel<<<dim3(BB, 16), 256>>>();
    gate_kernel<<<BB, 128>>>(g1_w, g1_b, g2_w, g2_b);
    dt_kernel<<<(BB*LL)/64, 256>>>(dt_w, dt_b);
    scan_kernel<<<BB*8, 256>>>(x, A, D, out);
}

// round 4
// speedup vs baseline: 1.9307x; 1.5710x over previous
#include <cuda_runtime.h>
#include <cuda_bf16.h>
#include <cstdint>

#define BB 16
#define CC_ 128
#define HH 64
#define WW 64
#define SS 16
#define LL (HH*WW)
#define NSEG 32
#define SEGLEN 128

// ---------------------------------------------------------------------------
// Scratch (no allocations allowed)
__device__ float g_xc[BB*LL*CC_];                         // conv output [b][l][c]
__device__ float g_dt[BB*LL*CC_];                         // dt sigmoid [b][l][c]
__device__ float g_pooled[BB*CC_];
__device__ float g_gate[BB*CC_];
__device__ __align__(16) __nv_bfloat16 g_xpad[BB*66*66*256];   // [b][r][c][hi128|lo128]
__device__ __align__(16) __nv_bfloat16 g_wp[9*2*128*128];      // [tap][var][co][ci]
__device__ float g_C[BB*CC_*NSEG*SS];     // per-seg local end state
__device__ float g_Sdt[BB*CC_*NSEG];      // per-seg sum of dt
__device__ float g_hin[BB*CC_*NSEG*SS];   // per-seg incoming state

// ---------------------------------------------------------------------------
__device__ __forceinline__ uint32_t smem_u32(const void* p) {
    uint32_t a;
    asm("{ .reg .u64 t; cvta.to.shared.u64 t, %1; cvt.u32.u64 %0, t; }" : "=r"(a) : "l"(p));
    return a;
}
__device__ __forceinline__ void cp16(uint32_t dst, const void* src) {
    asm volatile("cp.async.cg.shared.global [%0], [%1], 16;" :: "r"(dst), "l"(src));
}
__device__ __forceinline__ void cp_commit() { asm volatile("cp.async.commit_group;" ::: "memory"); }
template<int N> __device__ __forceinline__ void cp_wait() {
    asm volatile("cp.async.wait_group %0;" :: "n"(N) : "memory");
}
__device__ __forceinline__ void ldsm_x4(uint32_t& r0, uint32_t& r1, uint32_t& r2, uint32_t& r3, uint32_t addr) {
    asm volatile("ldmatrix.sync.aligned.m8n8.x4.shared.b16 {%0,%1,%2,%3}, [%4];"
        : "=r"(r0), "=r"(r1), "=r"(r2), "=r"(r3) : "r"(addr));
}
__device__ __forceinline__ void mma16816(float* c, uint32_t a0, uint32_t a1, uint32_t a2, uint32_t a3,
                                         uint32_t b0, uint32_t b1) {
    asm volatile("mma.sync.aligned.m16n8k16.row.col.f32.bf16.bf16.f32 "
        "{%0,%1,%2,%3}, {%4,%5,%6,%7}, {%8,%9}, {%0,%1,%2,%3};"
        : "+f"(c[0]), "+f"(c[1]), "+f"(c[2]), "+f"(c[3])
        : "r"(a0), "r"(a1), "r"(a2), "r"(a3), "r"(b0), "r"(b1));
}

// ---------------------------------------------------------------------------
__global__ void zero_pooled_kernel() {
    int i = blockIdx.x * blockDim.x + threadIdx.x;
    if (i < BB*CC_) g_pooled[i] = 0.f;
}

// ---------------------------------------------------------------------------
// prep_x: x (fp32 NCHW) -> padded channels-last bf16 hi/lo [b][66][66][256]
__global__ __launch_bounds__(256) void prep_x_kernel(const float* __restrict__ x)
{
    const int pr = blockIdx.x;   // padded row 0..65
    const int b  = blockIdx.y;
    const int tid = threadIdx.x;
    uint32_t* outw = reinterpret_cast<uint32_t*>(g_xpad) + ((b*66 + pr)*66) * 128;

    if (pr == 0 || pr == 65) {
        for (int i = tid; i < 66*128; i += 256) outw[i] = 0u;
        return;
    }
    const int hr = pr - 1;
    __shared__ float tile[128*64];
    for (int i = tid; i < 128*64; i += 256) {
        int c = i >> 6, w = i & 63;
        tile[i] = x[((b*CC_ + c)*HH + hr)*WW + w];
    }
    __syncthreads();
    for (int i = tid; i < 66*128; i += 256) {
        int pc = i >> 7, j = i & 127;
        uint32_t v = 0u;
        if (pc >= 1 && pc <= 64) {
            int w = pc - 1;
            int c0 = (j < 64) ? (j*2) : ((j-64)*2);
            float v0 = tile[c0*64 + w], v1 = tile[(c0+1)*64 + w];
            __nv_bfloat16 h0 = __float2bfloat16(v0), h1 = __float2bfloat16(v1);
            __nv_bfloat16 o0, o1;
            if (j < 64) { o0 = h0; o1 = h1; }
            else {
                o0 = __float2bfloat16(v0 - __bfloat162float(h0));
                o1 = __float2bfloat16(v1 - __bfloat162float(h1));
            }
            v = (uint32_t)*reinterpret_cast<uint16_t*>(&o0) |
                ((uint32_t)*reinterpret_cast<uint16_t*>(&o1) << 16);
        }
        outw[i] = v;
    }
}

// prep_w: conv_w [co][ci][3][3] fp32 -> g_wp[tap][var][co][ci] bf16 (var0=hi, var1=lo)
__global__ __launch_bounds__(256) void prep_w_kernel(const float* __restrict__ cw)
{
    int idx = blockIdx.x * 256 + threadIdx.x;
    if (idx >= 9*2*128*128) return;
    int t   = idx >> 15;
    int var = (idx >> 14) & 1;
    int co  = (idx >> 7) & 127;
    int ci  = idx & 127;
    float w = cw[(co*CC_ + ci)*9 + t];
    __nv_bfloat16 hi = __float2bfloat16(w);
    g_wp[idx] = (var == 0) ? hi : __float2bfloat16(w - __bfloat162float(hi));
}

// ---------------------------------------------------------------------------
// Implicit-GEMM conv via warp-level HMMA (mma.sync m16n8k16 bf16).
#define ROWSTRIDE 144

__global__ __launch_bounds__(256, 2) void conv_mma_kernel(const float* __restrict__ cbias)
{
    extern __shared__ char dyn[];
    const uint32_t sbase = smem_u32(dyn);
    const uint32_t abuf[2] = { sbase,           sbase + 36864 };
    const uint32_t bbuf[2] = { sbase + 18432,   sbase + 36864 + 18432 };

    const int tid  = threadIdx.x;
    const int wid  = tid >> 5;
    const int lane = tid & 31;
    const int mw   = wid & 3;
    const int nw   = wid >> 2;
    const int b    = blockIdx.x >> 5;
    const int tile = blockIdx.x & 31;
    const int R    = tile * 2;

    float acc[2][8][4];
#pragma unroll
    for (int m = 0; m < 2; m++)
#pragma unroll
        for (int n = 0; n < 8; n++)
#pragma unroll
            for (int j = 0; j < 4; j++) acc[m][n][j] = 0.f;

    const __nv_bfloat16* xp = g_xpad;
    const __nv_bfloat16* wp = g_wp;

    auto issue_loads = [&](int s, uint32_t ab, uint32_t bb) {
        const int t_  = s / 6;
        const int sub = s - t_*6;
        const int kh  = t_ / 3, kw = t_ - kh*3;
        const int choff = ((sub >= 2 && sub < 4) ? 128 : 0) + ((sub & 1) << 6);
        const int cioff = (sub & 1) << 6;
        const int var   = (sub >= 4) ? 1 : 0;
        const __nv_bfloat16* wrow = wp + (long)((t_*2 + var)*128) * 128 + cioff;
#pragma unroll
        for (int i = 0; i < 4; i++) {
            int idx = tid + i*256;
            int tk  = idx >> 3;
            int k8  = idx & 7;
            {
                int prow = R + kh + (tk >> 6);
                int pcol = kw + (tk & 63);
                long gi = ((long)((b*66 + prow)*66 + pcol) << 8) + choff + (k8 << 3);
                cp16(ab + tk*ROWSTRIDE + k8*16, xp + gi);
            }
            cp16(bb + tk*ROWSTRIDE + k8*16, wrow + (long)tk*128 + (k8 << 3));
        }
    };

    issue_loads(0, abuf[0], bbuf[0]);
    cp_commit();

    const uint32_t lrow = (lane & 15);
    const uint32_t lhalf = (lane >> 4) * 16;

    for (int s = 0; s < 54; s++) {
        if (s + 1 < 54) {
            int bn = (s + 1) & 1;
            issue_loads(s + 1, abuf[bn], bbuf[bn]);
            cp_commit();
            cp_wait<1>();
        } else {
            cp_wait<0>();
        }
        __syncthreads();

        const uint32_t ab = abuf[s & 1], bb = bbuf[s & 1];
        const uint32_t a0 = ab + (mw*32 + lrow)*ROWSTRIDE + lhalf;
        const uint32_t a1 = ab + (mw*32 + 16 + lrow)*ROWSTRIDE + lhalf;
        const uint32_t bbase = bb + (nw*64 + lrow)*ROWSTRIDE + lhalf;

#pragma unroll
        for (int ks = 0; ks < 4; ks++) {
            uint32_t af[2][4];
            ldsm_x4(af[0][0], af[0][1], af[0][2], af[0][3], a0 + ks*32);
            ldsm_x4(af[1][0], af[1][1], af[1][2], af[1][3], a1 + ks*32);
            uint32_t bf[8][2];
#pragma unroll
            for (int q = 0; q < 4; q++) {
                uint32_t r0, r1, r2, r3;
                ldsm_x4(r0, r1, r2, r3, bbase + q*16*ROWSTRIDE + ks*32);
                bf[q*2][0] = r0;   bf[q*2][1] = r2;
                bf[q*2+1][0] = r1; bf[q*2+1][1] = r3;
            }
#pragma unroll
            for (int m = 0; m < 2; m++)
#pragma unroll
                for (int n = 0; n < 8; n++)
                    mma16816(acc[m][n], af[m][0], af[m][1], af[m][2], af[m][3],
                             bf[n][0], bf[n][1]);
        }
        __syncthreads();
    }

    const int qrow = lane >> 2;
    const int qcol = (lane & 3) * 2;
    const long tokbase = (long)(b << 12) + tile*128 + mw*32;
#pragma unroll
    for (int n = 0; n < 8; n++) {
        const int co = nw*64 + n*8 + qcol;
        const float b0 = cbias[co], b1 = cbias[co + 1];
#pragma unroll
        for (int m = 0; m < 2; m++) {
            long t0 = tokbase + m*16 + qrow;
            float2 v0 = make_float2(acc[m][n][0] + b0, acc[m][n][1] + b1);
            float2 v1 = make_float2(acc[m][n][2] + b0, acc[m][n][3] + b1);
            *reinterpret_cast<float2*>(g_xc + t0*CC_ + co) = v0;
            *reinterpret_cast<float2*>(g_xc + (t0 + 8)*CC_ + co) = v1;
        }
    }
}

// ---------------------------------------------------------------------------
__global__ __launch_bounds__(256) void pool_kernel()
{
    const int b  = blockIdx.x;
    const int lc = blockIdx.y;
    const int tid = threadIdx.x;
    const int c = tid & 127, half = tid >> 7;
    float s = 0.f;
    for (int l = lc*256 + half; l < lc*256 + 256; l += 2)
        s += g_xc[((long)(b << 12) + l)*CC_ + c];
    __shared__ float sp[256];
    sp[tid] = s;
    __syncthreads();
    if (tid < 128) atomicAdd(&g_pooled[b*CC_ + tid], sp[tid] + sp[tid + 128]);
}

// ---------------------------------------------------------------------------
__global__ __launch_bounds__(128) void gate_kernel(
    const float* __restrict__ g1w, const float* __restrict__ g1b,
    const float* __restrict__ g2w, const float* __restrict__ g2b)
{
    const int b = blockIdx.x;
    const int o = threadIdx.x;
    __shared__ float sp[CC_], st[CC_];
    sp[o] = g_pooled[b*CC_ + o] * (1.f/(float)LL);
    __syncthreads();
    float a1 = g1b[o];
    for (int c = 0; c < CC_; c++) a1 = fmaf(sp[c], g1w[o*CC_ + c], a1);
    st[o] = fmaxf(a1, 0.f);
    __syncthreads();
    float a2 = g2b[o];
    for (int c = 0; c < CC_; c++) a2 = fmaf(st[c], g2w[o*CC_ + c], a2);
    g_gate[b*CC_ + o] = 1.f / (1.f + __expf(-a2));
}

// ---------------------------------------------------------------------------
__global__ __launch_bounds__(256) void dt_kernel(
    const float* __restrict__ dtw, const float* __restrict__ dtb)
{
    const int m0   = blockIdx.x * 64;
    const int b    = m0 >> 12;
    const int tid  = threadIdx.x;
    const int colg = tid & 31;
    const int rowg = tid >> 5;

    __shared__ float xs[64*33];
    __shared__ float ws[128*33];

    float acc[8][4];
#pragma unroll
    for (int p = 0; p < 8; p++)
#pragma unroll
        for (int j = 0; j < 4; j++) acc[p][j] = 0.f;

    for (int kb = 0; kb < CC_; kb += 32) {
        __syncthreads();
        for (int idx = tid; idx < 64*32; idx += 256) {
            int rr = idx >> 5, k = idx & 31;
            xs[rr*33 + k] = g_xc[(m0+rr)*CC_ + kb + k] * g_gate[b*CC_ + kb + k];
        }
        for (int idx = tid; idx < 128*32; idx += 256) {
            int co = idx >> 5, k = idx & 31;
            ws[co*33 + k] = dtw[co*CC_ + kb + k];
        }
        __syncthreads();
#pragma unroll
        for (int k = 0; k < 32; k++) {
            float xv[8], wv[4];
#pragma unroll
            for (int p = 0; p < 8; p++) xv[p] = xs[(rowg*8+p)*33 + k];
#pragma unroll
            for (int j = 0; j < 4; j++) wv[j] = ws[(colg*4+j)*33 + k];
#pragma unroll
            for (int p = 0; p < 8; p++)
#pragma unroll
                for (int j = 0; j < 4; j++)
                    acc[p][j] = fmaf(xv[p], wv[j], acc[p][j]);
        }
    }
#pragma unroll
    for (int p = 0; p < 8; p++) {
        float4 v;
        float* vv = reinterpret_cast<float*>(&v);
#pragma unroll
        for (int j = 0; j < 4; j++) {
            float z = acc[p][j] + dtb[colg*4 + j];
            vv[j] = 1.f / (1.f + __expf(-z));
        }
        *reinterpret_cast<float4*>(&g_dt[(m0 + rowg*8 + p)*CC_ + colg*4]) = v;
    }
}

// ---------------------------------------------------------------------------
// SSM parallel scan, pass 1: per (b,c,seg) local scan from h=0.
// Thread = one channel c; block = (b, seg); 128 threads.
__global__ __launch_bounds__(128) void scan_p1_kernel(const float* __restrict__ Araw)
{
    const int b   = blockIdx.x >> 5;
    const int seg = blockIdx.x & 31;
    const int c   = threadIdx.x;

    const float gc = g_gate[b*CC_ + c];
    float An[SS], h[SS];
#pragma unroll
    for (int s = 0; s < SS; s++) { An[s] = -__expf(Araw[c*SS + s]); h[s] = 0.f; }

    const float* xcp = g_xc + ((long)(b*LL) + seg*SEGLEN)*CC_ + c;
    const float* dtp = g_dt + ((long)(b*LL) + seg*SEGLEN)*CC_ + c;
    float sdt = 0.f;

    for (int t = 0; t < SEGLEN; t++) {
        float xv  = xcp[t*CC_] * gc;
        float dtv = dtp[t*CC_];
        sdt += dtv;
#pragma unroll
        for (int s = 0; s < SS; s++)
            h[s] = fmaf(h[s], __expf(An[s]*dtv), xv);
    }
    const long pair = (long)b*CC_ + c;
    float* Cp = g_C + (pair*NSEG + seg)*SS;
#pragma unroll
    for (int s = 0; s < SS; s++) Cp[s] = h[s];
    g_Sdt[pair*NSEG + seg] = sdt;
}

// pass 2: per (b,c) serial scan over 32 segment summaries.
// 256 threads = 16 (b,c)-pairs x 16 state-lanes.
__global__ __launch_bounds__(256) void scan_fix_kernel(const float* __restrict__ Araw)
{
    const int pair = blockIdx.x*16 + (threadIdx.x >> 4);   // b*128+c
    const int s    = threadIdx.x & 15;
    const int c    = pair & 127;
    const float An_s = -__expf(Araw[c*SS + s]);

    float h = 0.f;
    const float* Cp = g_C + (long)pair*NSEG*SS;
    const float* Sp = g_Sdt + (long)pair*NSEG;
    float* Hp = g_hin + (long)pair*NSEG*SS;
#pragma unroll 4
    for (int k = 0; k < NSEG; k++) {
        Hp[k*SS + s] = h;
        h = fmaf(h, __expf(An_s * Sp[k]), Cp[k*SS + s]);
    }
}

// pass 3: rerun each segment from correct h_in, produce y, write NCHW + identity.
__global__ __launch_bounds__(128) void scan_p3_kernel(
    const float* __restrict__ x0,
    const float* __restrict__ Araw,
    const float* __restrict__ Draw,
    float* __restrict__ out)
{
    const int b   = blockIdx.x >> 5;
    const int seg = blockIdx.x & 31;
    const int c   = threadIdx.x;
    const int lane = c & 31;
    const int wrp  = c >> 5;

    __shared__ float ybuf[32][129];

    const float gc = g_gate[b*CC_ + c];
    const float Dp = __expf(Draw[c]);
    float An[SS], h[SS];
    const long pair = (long)b*CC_ + c;
    const float* Hp = g_hin + (pair*NSEG + seg)*SS;
#pragma unroll
    for (int s = 0; s < SS; s++) { An[s] = -__expf(Araw[c*SS + s]); h[s] = Hp[s]; }

    const float* xcp = g_xc + ((long)(b*LL) + seg*SEGLEN)*CC_ + c;
    const float* dtp = g_dt + ((long)(b*LL) + seg*SEGLEN)*CC_ + c;
    const long l0 = seg*SEGLEN;

    for (int ch = 0; ch < SEGLEN/32; ch++) {
#pragma unroll 2
        for (int t = 0; t < 32; t++) {
            int tt = ch*32 + t;
            float xv  = xcp[tt*CC_] * gc;
            float dtv = dtp[tt*CC_];
            float y = Dp * xv;
#pragma unroll
            for (int s = 0; s < SS; s++) {
                h[s] = fmaf(h[s], __expf(An[s]*dtv), xv);
                y = fmaf(h[s], An[s], y);
            }
            ybuf[t][c] = y;
        }
        __syncthreads();
        // write out: warp w handles channels w*32..w*32+31, lane = token offset
#pragma unroll 4
        for (int cc = 0; cc < 32; cc++) {
            int co = wrp*32 + cc;
            long gidx = ((long)(b*CC_ + co) << 12) + l0 + ch*32 + lane;
            out[gidx] = ybuf[lane][co] + x0[gidx];
        }
        __syncthreads();
    }
}

// ---------------------------------------------------------------------------
extern "C" void kernel_launch(void* const* d_in, const int* in_sizes, int n_in,
                              void* d_out, int out_size)
{
    const float* x      = (const float*)d_in[0];
    const float* conv_w = (const float*)d_in[1];
    const float* conv_b = (const float*)d_in[2];
    const float* dt_w   = (const float*)d_in[3];
    const float* dt_b   = (const float*)d_in[4];
    const float* A      = (const float*)d_in[5];
    const float* D      = (const float*)d_in[6];
    const float* g1_w   = (const float*)d_in[7];
    const float* g1_b   = (const float*)d_in[8];
    const float* g2_w   = (const float*)d_in[9];
    const float* g2_b   = (const float*)d_in[10];
    float* out = (float*)d_out;

    const int conv_smem = 2 * (18432 + 18432);
    cudaFuncSetAttribute(conv_mma_kernel, cudaFuncAttributeMaxDynamicSharedMemorySize, conv_smem);

    zero_pooled_kernel<<<8, 256>>>();
    prep_x_kernel<<<dim3(66, BB), 256>>>(x);
    prep_w_kernel<<<(9*2*128*128 + 255)/256, 256>>>(conv_w);
    conv_mma_kernel<<<BB*32, 256, conv_smem>>>(conv_b);
    pool_kernel<<<dim3(BB, 16), 256>>>();
    gate_kernel<<<BB, 128>>>(g1_w, g1_b, g2_w, g2_b);
    dt_kernel<<<(BB*LL)/64, 256>>>(dt_w, dt_b);
    scan_p1_kernel<<<BB*NSEG, 128>>>(A);
    scan_fix_kernel<<<BB*CC_/16, 256>>>(A);
    scan_p3_kernel<<<BB*NSEG, 128>>>(x, A, D, out);
}